// round 15
// baseline (speedup 1.0000x reference)
#include <cuda_runtime.h>
#include <cstdint>

// Horizontal correlation cost volume via banded tf32 mma.sync GEMM.
// a,b: fp32 [B=8, C=128, H=192, W=256], D=40.
// out[bi, ctr, h, w] = sum_c a[bi,c,h,w] * bp[bi,c,h, ctr+w], bp left-padded by 40.
//
// 16 CTAs/SM x 64 threads: each CTA owns an EIGHTH row (32 w's), grid=12288.
// Domain-splitting law measured R11->R14: each doubling of independent
// barrier/cp.async domains per SM buys ~2 DRAM pts (77.6 -> 78.8 -> 82.1%);
// L2 dedups the b-window overlap between adjacent-eighth CTAs so DRAM bytes
// stay compulsory.
//
// 2 warps, warp = one 16-wide w tile; 7 n-tiles of 8 per warp (diagonal band).
// m16n8k8 tf32 mma, cvt.rna.tf32.f32 operands.
// CC=8 / NSTAGE=4 / PFD=2 single-barrier pipeline:
//   per chunk: prefetch(ch+2) -> cp.async.wait_group 2 -> __syncthreads -> compute
// (stage overwritten at iter ch last read at compute(ch-2), ordered by
//  barrier(ch-1) since NSTAGE = PFD+2). Prefetch coords precomputed; loop
// fully unrolled.
//
// Pitches: A_PITCH=40, B_PITCH=72, both == 8 (mod 32) -> fragment LDS banks
// 8q+r0, conflict-free. Pad-zeroing generalized: npad = max(0, 10 - hb/4)
// blocks per b channel per stage (eighth 0: 10, eighth 1: 2, others: 0).
// Epilogue: band-extract into a 41x36 smem tile (reuses ring), float4 .cs stores.

#define C_TOT   128
#define W_DIM   256
#define H_DIM   192
#define B_DIM   8
#define NCTR    41
#define NT      64
#define CC      8
#define NCHUNK  (C_TOT / CC)       // 16
#define NSTAGE  4
#define PFD     2

#define A_PITCH 40                 // 32 data + 8 pad    (40 mod 32 = 8)
#define B_PITCH 72                 // 72 window floats   (72 mod 32 = 8)
#define BBLKS   18                 // float4 blocks per b channel row
#define STAGE_F (CC * (A_PITCH + B_PITCH))   // 896 floats per stage
#define B_OFF   (CC * A_PITCH)               // 320 floats
#define OUT_PITCH 36                         // 36 mod 32 = 4
#define RING_F  (NSTAGE * STAGE_F)           // 3584 floats
#define SMEM_BYTES (RING_F * 4)              // 14336 B (> 41*36*4 = 5904)

__device__ __forceinline__ void cpasync16(uint32_t dst, const void* src) {
    asm volatile("cp.async.cg.shared.global [%0], [%1], 16;\n" :: "r"(dst), "l"(src));
}
__device__ __forceinline__ void cp_commit() {
    asm volatile("cp.async.commit_group;\n");
}
__device__ __forceinline__ void cp_wait2() {
    asm volatile("cp.async.wait_group 2;\n" ::: "memory");
}
__device__ __forceinline__ uint32_t to_tf32(float f) {
    uint32_t u;
    asm("cvt.rna.tf32.f32 %0, %1;" : "=r"(u) : "f"(f));
    return u;
}
__device__ __forceinline__ void mma_tf32(float& d0, float& d1, float& d2, float& d3,
                                         uint32_t a0, uint32_t a1, uint32_t a2, uint32_t a3,
                                         uint32_t b0, uint32_t b1) {
    asm volatile("mma.sync.aligned.m16n8k8.row.col.f32.tf32.tf32.f32 "
                 "{%0,%1,%2,%3}, {%4,%5,%6,%7}, {%8,%9}, {%0,%1,%2,%3};\n"
                 : "+f"(d0), "+f"(d1), "+f"(d2), "+f"(d3)
                 : "r"(a0), "r"(a1), "r"(a2), "r"(a3), "r"(b0), "r"(b1));
}
__device__ __forceinline__ void stg_cs_v4(float* p, float x, float y, float z, float w) {
    asm volatile("st.global.cs.v4.f32 [%0], {%1, %2, %3, %4};\n"
                 :: "l"(p), "f"(x), "f"(y), "f"(z), "f"(w) : "memory");
}

__global__ __launch_bounds__(NT, 16)
void corr_kernel(const float* __restrict__ A,
                 const float* __restrict__ B,
                 float* __restrict__ O)
{
    extern __shared__ __align__(16) float sm[];

    const int bidx = blockIdx.x;
    const int row  = bidx >> 3;                // (bi,h) row
    const int egt  = bidx & 7;                 // which w-eighth
    const int bi   = row / H_DIM;
    const int h    = row - bi * H_DIM;
    const int hb   = egt * 32;                 // w base of this CTA

    const int tid  = threadIdx.x;
    const int wid  = tid >> 5;                 // 0..1 -> local w tile
    const int lane = tid & 31;
    const int WL   = wid * 16;                 // local w base of this warp
    const int q    = lane & 3;
    const int r0   = lane >> 2;

    const size_t plane = (size_t)H_DIM * W_DIM;
    const float* Arow = A + ((size_t)bi * C_TOT * H_DIM + h) * W_DIM;
    const float* Brow = B + ((size_t)bi * C_TOT * H_DIM + h) * W_DIM;

    const uint32_t smb = (uint32_t)__cvta_generic_to_shared(sm);

    const int bsrc_base = (hb >> 2) - 10;      // b source block of local block 0
    const int npad = (bsrc_base < 0) ? -bsrc_base : 0;   // leading pad blocks

    // ---- zero the permanent pad blocks per b channel per stage (once) ----
    if (npad > 0) {
        const int per_stage = CC * npad;
        for (int t = tid; t < NSTAGE * per_stage; t += NT) {
            int st = t / per_stage;
            int u  = t - st * per_stage;
            int c  = u / npad;
            int l  = u - c * npad;
            float4* p = (float4*)(sm + st * STAGE_F + B_OFF + c * B_PITCH) + l;
            *p = make_float4(0.f, 0.f, 0.f, 0.f);
        }
    }

    float acc[7][4];
#pragma unroll
    for (int jt = 0; jt < 7; ++jt)
#pragma unroll
        for (int k = 0; k < 4; ++k) acc[jt][k] = 0.0f;

    // ---- precomputed prefetch coordinates (fixed per thread) ----
    const size_t chstep = (size_t)CC * plane;

    // a copy: 8 ch x 8 blocks = 64 = NT
    const int ac = tid >> 3, ablk = tid & 7;
    const float*  asrc = Arow + (size_t)ac * plane + hb + ablk * 4;
    const uint32_t adst = smb + (ac * A_PITCH) * 4 + ablk * 16;

    // b copies: 8 ch x 18 blocks = 144 = 64 + 64 + 16
    const int i1 = tid;
    const int c1 = i1 / BBLKS, l1 = i1 - c1 * BBLKS;
    const int g1 = bsrc_base + l1;
    const bool v1 = (g1 >= 0);
    const float*  bsrc1 = Brow + (size_t)c1 * plane + g1 * 4;
    const uint32_t bdst1 = smb + (B_OFF + c1 * B_PITCH) * 4 + l1 * 16;

    const int i2 = tid + NT;
    const int c2 = i2 / BBLKS, l2 = i2 - c2 * BBLKS;
    const int g2 = bsrc_base + l2;
    const bool v2 = (g2 >= 0);
    const float*  bsrc2 = Brow + (size_t)c2 * plane + g2 * 4;
    const uint32_t bdst2 = smb + (B_OFF + c2 * B_PITCH) * 4 + l2 * 16;

    const int i3 = tid + 2 * NT;               // valid only for tid < 16
    const int c3 = i3 / BBLKS, l3 = i3 - c3 * BBLKS;
    const int g3 = bsrc_base + l3;
    const bool v3 = (i3 < CC * BBLKS) && (g3 >= 0);
    const float*  bsrc3 = Brow + (size_t)c3 * plane + g3 * 4;
    const uint32_t bdst3 = smb + (B_OFF + c3 * B_PITCH) * 4 + l3 * 16;

    auto prefetch = [&](int ch, uint32_t so) {
        const size_t off = (size_t)ch * chstep;
        cpasync16(adst + so, asrc + off);
        if (v1) cpasync16(bdst1 + so, bsrc1 + off);
        if (v2) cpasync16(bdst2 + so, bsrc2 + off);
        if (v3) cpasync16(bdst3 + so, bsrc3 + off);
        cp_commit();
    };

#pragma unroll
    for (int p = 0; p < PFD; ++p) prefetch(p, p * STAGE_F * 4);

#pragma unroll
    for (int ch = 0; ch < NCHUNK; ++ch) {
        // prefetch FIRST: stage (ch+PFD)%NSTAGE last read at compute(ch-2),
        // ordered by barrier(ch-1) since NSTAGE = PFD+2.
        if (ch + PFD < NCHUNK)
            prefetch(ch + PFD, ((ch + PFD) % NSTAGE) * STAGE_F * 4);
        else
            cp_commit();                       // empty group keeps FIFO invariant

        cp_wait2();        // this thread's copies for chunk ch complete
        __syncthreads();   // publish all threads' copies

        const float* as = sm + (ch % NSTAGE) * STAGE_F;   // immediate after unroll
        const float* bs = as + B_OFF;

        uint32_t a0 = to_tf32(as[q * A_PITCH + WL + r0]);
        uint32_t a1 = to_tf32(as[q * A_PITCH + WL + r0 + 8]);
        uint32_t a2 = to_tf32(as[(q + 4) * A_PITCH + WL + r0]);
        uint32_t a3 = to_tf32(as[(q + 4) * A_PITCH + WL + r0 + 8]);

#pragma unroll
        for (int jt = 0; jt < 7; ++jt) {
            int j = WL + jt * 8 + r0;          // local bp index, max 71
            uint32_t b0 = to_tf32(bs[q * B_PITCH + j]);
            uint32_t b1 = to_tf32(bs[(q + 4) * B_PITCH + j]);
            mma_tf32(acc[jt][0], acc[jt][1], acc[jt][2], acc[jt][3],
                     a0, a1, a2, a3, b0, b1);
        }
    }

    // ---- band extraction into smem: out_s[ctr][w_local] (reuses ring smem) ----
    __syncthreads();
#pragma unroll
    for (int jt = 0; jt < 7; ++jt) {
        int nb = jt * 8 + 2 * q;
        int ctr00 = nb - r0;
        int ctr10 = nb - (r0 + 8);
        if (ctr00 >= 0 && ctr00 <= 40)         sm[ctr00 * OUT_PITCH + WL + r0]           = acc[jt][0];
        if (ctr00 + 1 >= 0 && ctr00 + 1 <= 40) sm[(ctr00 + 1) * OUT_PITCH + WL + r0]     = acc[jt][1];
        if (ctr10 >= 0 && ctr10 <= 40)         sm[ctr10 * OUT_PITCH + WL + r0 + 8]       = acc[jt][2];
        if (ctr10 + 1 >= 0 && ctr10 + 1 <= 40) sm[(ctr10 + 1) * OUT_PITCH + WL + r0 + 8] = acc[jt][3];
    }
    __syncthreads();

    // ---- write-out: 41 x 8 float4, streaming (.cs) stores ----
    for (int idx = tid; idx < NCTR * 8; idx += NT) {
        int ctr = idx >> 3;
        int blk = idx & 7;
        const float* s = sm + ctr * OUT_PITCH + blk * 4;
        float* dst = O + (((size_t)bi * NCTR + ctr) * H_DIM + h) * W_DIM + hb + blk * 4;
        stg_cs_v4(dst, s[0], s[1], s[2], s[3]);
    }
}

extern "C" void kernel_launch(void* const* d_in, const int* in_sizes, int n_in,
                              void* d_out, int out_size)
{
    const float* a = (const float*)d_in[0];
    const float* b = (const float*)d_in[1];
    float* out = (float*)d_out;

    cudaFuncSetAttribute(corr_kernel,
                         cudaFuncAttributeMaxDynamicSharedMemorySize, SMEM_BYTES);

    dim3 grid(B_DIM * H_DIM * 8);   // 12288 CTAs, one per (batch, h, w-eighth)
    dim3 block(NT);
    corr_kernel<<<grid, block, SMEM_BYTES>>>(a, b, out);
}

// round 17
// speedup vs baseline: 1.3118x; 1.3118x over previous
#include <cuda_runtime.h>
#include <cstdint>

// Horizontal correlation cost volume via banded tf32 mma.sync GEMM.
// a,b: fp32 [B=8, C=128, H=192, W=256], D=40.
// out[bi, ctr, h, w] = sum_c a[bi,c,h,w] * bp[bi,c,h, ctr+w], bp left-padded by 40.
//
// 8 CTAs/SM x 128 threads: each CTA owns a QUARTER row (64 w's), grid=6144.
// Measured optimum of the domain-splitting axis (2/4/8/16 CTAs/SM: 77.6 /
// 78.8 / 82.1% DRAM / regression). L2 dedups the b-window overlap between
// adjacent-quarter CTAs so DRAM bytes stay compulsory (~452MB).
//
// 4 warps, warp = one 16-wide w tile; 7 n-tiles of 8 per warp (diagonal band).
// m16n8k8 tf32 mma, cvt.rna.tf32.f32 operands.
// CC=8 / NSTAGE=5 / PFD=3 single-barrier pipeline:
//   per chunk: prefetch(ch+3) -> cp.async.wait_group 3 -> __syncthreads -> compute
// (stage overwritten at iter ch last read at compute(ch-2), ordered by
//  barrier(ch-1) since NSTAGE = PFD+2). Prefetch coords precomputed; loop
// fully unrolled (stage offsets are immediates).
//
// Pitches: A_PITCH=72, B_PITCH=104, both == 8 (mod 32) -> fragment LDS banks
// 8q+r0, conflict-free. Epilogue: band-extract into a 41x68 smem tile
// (reuses ring smem), then unrolled coalesced float4 .cs stores
// (QUARTER-row geometry: 16 blocks/ctr, blk = tid&15 -- R16 wrongly used 32).

#define C_TOT   128
#define W_DIM   256
#define H_DIM   192
#define B_DIM   8
#define NCTR    41
#define NT      128
#define CC      8
#define NCHUNK  (C_TOT / CC)       // 16
#define NSTAGE  5
#define PFD     3

#define A_PITCH 72                 // 64 data + 8 pad    (72 mod 32 = 8)
#define B_PITCH 104                // 104 window floats  (104 mod 32 = 8)
#define BBLKS   26                 // float4 blocks per b channel row
#define STAGE_F (CC * (A_PITCH + B_PITCH))   // 1408 floats per stage
#define B_OFF   (CC * A_PITCH)               // 576 floats
#define OUT_PITCH 68                         // 68 mod 32 = 4
#define RING_F  (NSTAGE * STAGE_F)           // 7040 floats
#define SMEM_BYTES (RING_F * 4)              // 28160 B (> 41*68*4 = 11152)

__device__ __forceinline__ void cpasync16(uint32_t dst, const void* src) {
    asm volatile("cp.async.cg.shared.global [%0], [%1], 16;\n" :: "r"(dst), "l"(src));
}
__device__ __forceinline__ void cp_commit() {
    asm volatile("cp.async.commit_group;\n");
}
__device__ __forceinline__ void cp_wait3() {
    asm volatile("cp.async.wait_group 3;\n" ::: "memory");
}
__device__ __forceinline__ uint32_t to_tf32(float f) {
    uint32_t u;
    asm("cvt.rna.tf32.f32 %0, %1;" : "=r"(u) : "f"(f));
    return u;
}
__device__ __forceinline__ void mma_tf32(float& d0, float& d1, float& d2, float& d3,
                                         uint32_t a0, uint32_t a1, uint32_t a2, uint32_t a3,
                                         uint32_t b0, uint32_t b1) {
    asm volatile("mma.sync.aligned.m16n8k8.row.col.f32.tf32.tf32.f32 "
                 "{%0,%1,%2,%3}, {%4,%5,%6,%7}, {%8,%9}, {%0,%1,%2,%3};\n"
                 : "+f"(d0), "+f"(d1), "+f"(d2), "+f"(d3)
                 : "r"(a0), "r"(a1), "r"(a2), "r"(a3), "r"(b0), "r"(b1));
}
__device__ __forceinline__ void stg_cs_v4(float* p, float x, float y, float z, float w) {
    asm volatile("st.global.cs.v4.f32 [%0], {%1, %2, %3, %4};\n"
                 :: "l"(p), "f"(x), "f"(y), "f"(z), "f"(w) : "memory");
}

__global__ __launch_bounds__(NT, 8)
void corr_kernel(const float* __restrict__ A,
                 const float* __restrict__ B,
                 float* __restrict__ O)
{
    extern __shared__ __align__(16) float sm[];

    const int bidx = blockIdx.x;
    const int row  = bidx >> 2;                // (bi,h) row
    const int qtr  = bidx & 3;                 // which w-quarter
    const int bi   = row / H_DIM;
    const int h    = row - bi * H_DIM;
    const int hb   = qtr * 64;                 // w base of this CTA

    const int tid  = threadIdx.x;
    const int wid  = tid >> 5;                 // 0..3 -> local w tile
    const int lane = tid & 31;
    const int WL   = wid * 16;                 // local w base of this warp
    const int q    = lane & 3;
    const int r0   = lane >> 2;

    const size_t plane = (size_t)H_DIM * W_DIM;
    const float* Arow = A + ((size_t)bi * C_TOT * H_DIM + h) * W_DIM;
    const float* Brow = B + ((size_t)bi * C_TOT * H_DIM + h) * W_DIM;

    const uint32_t smb = (uint32_t)__cvta_generic_to_shared(sm);

    // ---- qtr 0: zero the 10 permanent pad blocks per b channel per stage ----
    if (qtr == 0) {
        for (int t = tid; t < NSTAGE * CC * 10; t += NT) {
            int st = t / (CC * 10);
            int u  = t - st * (CC * 10);
            int c  = u / 10;
            int l  = u - c * 10;
            float4* p = (float4*)(sm + st * STAGE_F + B_OFF + c * B_PITCH) + l;
            *p = make_float4(0.f, 0.f, 0.f, 0.f);
        }
    }

    float acc[7][4];
#pragma unroll
    for (int jt = 0; jt < 7; ++jt)
#pragma unroll
        for (int k = 0; k < 4; ++k) acc[jt][k] = 0.0f;

    // ---- precomputed prefetch coordinates (fixed per thread) ----
    const int bsrc_base = (hb >> 2) - 10;      // b source block of local block 0
    const size_t chstep = (size_t)CC * plane;

    // a copy: 8 ch x 16 blocks = 128 = NT
    const int ac = tid >> 4, ablk = tid & 15;
    const float*  asrc = Arow + (size_t)ac * plane + hb + ablk * 4;
    const uint32_t adst = smb + (ac * A_PITCH) * 4 + ablk * 16;

    // b copies: 8 ch x 26 blocks = 208 = 128 + 80
    const int c1 = tid / BBLKS, l1 = tid - c1 * BBLKS;
    const int g1 = bsrc_base + l1;
    const bool v1 = (g1 >= 0);                 // false only for qtr 0's pads
    const float*  bsrc1 = Brow + (size_t)c1 * plane + g1 * 4;
    const uint32_t bdst1 = smb + (B_OFF + c1 * B_PITCH) * 4 + l1 * 16;

    const int idx2 = tid + NT;                 // 128..255, valid < 208
    const int c2 = idx2 / BBLKS, l2 = idx2 - c2 * BBLKS;
    const int g2 = bsrc_base + l2;
    const bool v2 = (idx2 < CC * BBLKS) && (g2 >= 0);
    const float*  bsrc2 = Brow + (size_t)c2 * plane + g2 * 4;
    const uint32_t bdst2 = smb + (B_OFF + c2 * B_PITCH) * 4 + l2 * 16;

    auto prefetch = [&](int ch, uint32_t so) {
        const size_t off = (size_t)ch * chstep;
        cpasync16(adst + so, asrc + off);
        if (v1) cpasync16(bdst1 + so, bsrc1 + off);
        if (v2) cpasync16(bdst2 + so, bsrc2 + off);
        cp_commit();
    };

#pragma unroll
    for (int p = 0; p < PFD; ++p) prefetch(p, p * STAGE_F * 4);

#pragma unroll
    for (int ch = 0; ch < NCHUNK; ++ch) {
        // prefetch FIRST: stage (ch+PFD)%NSTAGE last read at compute(ch-2),
        // ordered by barrier(ch-1) since NSTAGE = PFD+2.
        if (ch + PFD < NCHUNK)
            prefetch(ch + PFD, ((ch + PFD) % NSTAGE) * STAGE_F * 4);
        else
            cp_commit();                       // empty group keeps FIFO invariant

        cp_wait3();        // this thread's copies for chunk ch complete
        __syncthreads();   // publish all threads' copies

        const float* as = sm + (ch % NSTAGE) * STAGE_F;   // immediate after unroll
        const float* bs = as + B_OFF;

        uint32_t a0 = to_tf32(as[q * A_PITCH + WL + r0]);
        uint32_t a1 = to_tf32(as[q * A_PITCH + WL + r0 + 8]);
        uint32_t a2 = to_tf32(as[(q + 4) * A_PITCH + WL + r0]);
        uint32_t a3 = to_tf32(as[(q + 4) * A_PITCH + WL + r0 + 8]);

#pragma unroll
        for (int jt = 0; jt < 7; ++jt) {
            int j = WL + jt * 8 + r0;          // local bp index, max 103
            uint32_t b0 = to_tf32(bs[q * B_PITCH + j]);
            uint32_t b1 = to_tf32(bs[(q + 4) * B_PITCH + j]);
            mma_tf32(acc[jt][0], acc[jt][1], acc[jt][2], acc[jt][3],
                     a0, a1, a2, a3, b0, b1);
        }
    }

    // ---- band extraction into smem: out_s[ctr][w_local] (reuses ring smem) ----
    __syncthreads();
#pragma unroll
    for (int jt = 0; jt < 7; ++jt) {
        int nb = jt * 8 + 2 * q;
        int ctr00 = nb - r0;
        int ctr10 = nb - (r0 + 8);
        if (ctr00 >= 0 && ctr00 <= 40)         sm[ctr00 * OUT_PITCH + WL + r0]           = acc[jt][0];
        if (ctr00 + 1 >= 0 && ctr00 + 1 <= 40) sm[(ctr00 + 1) * OUT_PITCH + WL + r0]     = acc[jt][1];
        if (ctr10 >= 0 && ctr10 <= 40)         sm[ctr10 * OUT_PITCH + WL + r0 + 8]       = acc[jt][2];
        if (ctr10 + 1 >= 0 && ctr10 + 1 <= 40) sm[(ctr10 + 1) * OUT_PITCH + WL + r0 + 8] = acc[jt][3];
    }
    __syncthreads();

    // ---- write-out: 41 ctrs x 16 float4 blocks, unrolled .cs stores ----
    // QUARTER-row geometry: blk = tid&15 (16 blocks = 64 w's per ctr),
    // ctr0 = tid>>4 (0..7), ctr = ctr0 + 8k for k=0..4 -> ctrs 0..39;
    // ctr 40 tail handled by the ctr0==0 threads.
    {
        const int blk  = tid & 15;
        const int ctr0 = tid >> 4;                       // 0..7
        float* drow = O + (((size_t)bi * NCTR + ctr0) * H_DIM + h) * W_DIM + hb + blk * 4;
        const float* srow = sm + ctr0 * OUT_PITCH + blk * 4;
        const size_t dstep = (size_t)8 * H_DIM * W_DIM;  // +8 ctrs in O
#pragma unroll
        for (int k = 0; k < 5; ++k) {                    // ctrs ctr0 + 8k (0..39)
            const float* s = srow + k * 8 * OUT_PITCH;
            stg_cs_v4(drow + k * dstep, s[0], s[1], s[2], s[3]);
        }
        if (ctr0 == 0) {                                 // ctr 40 tail
            const float* s = srow + 40 * OUT_PITCH;
            stg_cs_v4(drow + 5 * dstep, s[0], s[1], s[2], s[3]);
        }
    }
}

extern "C" void kernel_launch(void* const* d_in, const int* in_sizes, int n_in,
                              void* d_out, int out_size)
{
    const float* a = (const float*)d_in[0];
    const float* b = (const float*)d_in[1];
    float* out = (float*)d_out;

    cudaFuncSetAttribute(corr_kernel,
                         cudaFuncAttributeMaxDynamicSharedMemorySize, SMEM_BYTES);

    dim3 grid(B_DIM * H_DIM * 4);   // 6144 CTAs, one per (batch, h, w-quarter)
    dim3 block(NT);
    corr_kernel<<<grid, block, SMEM_BYTES>>>(a, b, out);
}